// round 17
// baseline (speedup 1.0000x reference)
#include <cuda_runtime.h>
#include <mma.h>
#include <cstdint>
#include <math.h>
using namespace nvcuda;

#define BATCH 64
#define C 128
#define MS 16384         // C*C
#define HW 3136
#define KSPLIT 7
#define KPART 448
#define NCHUNK 14
#define NUM_ITER 5
#define TRIU 8256
#define XTLD 132
#define SYTHR 320

__device__ float g_G[KSPLIT][BATCH][C][C];
__device__ float g_s[KSPLIT][BATCH][C];
__device__ float g_Gt[BATCH][TRIU];     // reduced Gram, triu-linear (upper only)
__device__ float g_mu[BATCH][C];
__device__ float g_tr[BATCH];
__device__ float g_Y[2][BATCH][MS];
__device__ float g_Z[2][BATCH][MS];
__device__ float g_W[BATCH][MS];

// SYRK: 10 super-tiles (2x2 blocks of 16x16 tiles) covering 8x8 upper tri
__constant__ int8_t u_SI[10] = {0,0,0,1,1,2, 0,1,2,3};
__constant__ int8_t u_SJ[10] = {1,2,3,2,3,3, 0,1,2,3};

__device__ __forceinline__ float rtf32(float f) {
    uint32_t u; asm("cvt.rna.tf32.f32 %0, %1;" : "=r"(u) : "f"(f));
    return __uint_as_float(u);
}
__device__ __forceinline__ void triu_ij(int pos, int& i, int& j) {
    i = (int)((257.0f - sqrtf(66049.0f - 8.0f * (float)pos)) * 0.5f);
    if (i < 0) i = 0;
    if (i > 127) i = 127;
    while (i > 0 && i * (257 - i) / 2 > pos) i--;
    while (i < 127 && (i + 1) * (257 - (i + 1)) / 2 <= pos) i++;
    j = i + (pos - i * (257 - i) / 2);
}

typedef wmma::fragment<wmma::accumulator, 16, 16, 8, float> AccFrag;
typedef wmma::fragment<wmma::matrix_a, 16, 16, 8, wmma::precision::tf32, wmma::row_major> AFragR;
typedef wmma::fragment<wmma::matrix_a, 16, 16, 8, wmma::precision::tf32, wmma::col_major> AFragC;
typedef wmma::fragment<wmma::matrix_b, 16, 16, 8, wmma::precision::tf32, wmma::row_major> BFragR;

// ===================== Kernel 1: SYRK (unchanged, measured best) ============
__global__ __launch_bounds__(SYTHR, 2)
void syrk_tc(const float* __restrict__ x) {
    __shared__ __align__(16) float Xt[2][32 * XTLD];
    const int ks = blockIdx.x, b = blockIdx.y;
    const int t = threadIdx.x, w = t >> 5;
    const float* xb = x + (size_t)b * C * HW + (size_t)ks * KPART;

    const int ti0 = u_SI[w] * 2, tj0 = u_SJ[w] * 2;
    const bool diag = (w >= 6);

    AccFrag acc[4];
#pragma unroll
    for (int s = 0; s < 4; s++) wmma::fill_fragment(acc[s], 0.0f);

    const bool ldr = (t < 256);
    const int r0 = t >> 3, seg = t & 7;
    float4 R[4];
    float rs[4] = {0.f, 0.f, 0.f, 0.f};
    if (ldr) {
#pragma unroll
        for (int q = 0; q < 4; q++)
            R[q] = *(const float4*)(xb + (size_t)(r0 + q * 32) * HW + seg * 4);
    }

    for (int c = 0; c < NCHUNK; c++) {
        float* buf = Xt[c & 1];
        if (ldr) {
#pragma unroll
            for (int q = 0; q < 4; q++) {
                const float4 v = R[q];
                rs[q] += v.x + v.y + v.z + v.w;
                const int col = r0 + q * 32;
                buf[(seg * 4 + 0) * XTLD + col] = rtf32(v.x);
                buf[(seg * 4 + 1) * XTLD + col] = rtf32(v.y);
                buf[(seg * 4 + 2) * XTLD + col] = rtf32(v.z);
                buf[(seg * 4 + 3) * XTLD + col] = rtf32(v.w);
            }
            if (c + 1 < NCHUNK) {
                const float* xc = xb + (c + 1) * 32 + seg * 4;
#pragma unroll
                for (int q = 0; q < 4; q++)
                    R[q] = *(const float4*)(xc + (size_t)(r0 + q * 32) * HW);
            }
        }
        __syncthreads();
#pragma unroll
        for (int kk0 = 0; kk0 < 32; kk0 += 8) {
            const float* kbase = buf + kk0 * XTLD;
            AFragC a0, a1; BFragR b0, b1;
            wmma::load_matrix_sync(a0, kbase + ti0 * 16, XTLD);
            wmma::load_matrix_sync(a1, kbase + ti0 * 16 + 16, XTLD);
            wmma::load_matrix_sync(b0, kbase + tj0 * 16, XTLD);
            wmma::load_matrix_sync(b1, kbase + tj0 * 16 + 16, XTLD);
            wmma::mma_sync(acc[0], a0, b0, acc[0]);
            wmma::mma_sync(acc[1], a0, b1, acc[1]);
            if (!diag) wmma::mma_sync(acc[2], a1, b0, acc[2]);
            wmma::mma_sync(acc[3], a1, b1, acc[3]);
        }
    }

    float* Gp = &g_G[ks][b][0][0];
    wmma::store_matrix_sync(Gp + ti0 * 16 * C + tj0 * 16, acc[0], C, wmma::mem_row_major);
    wmma::store_matrix_sync(Gp + ti0 * 16 * C + (tj0 + 1) * 16, acc[1], C, wmma::mem_row_major);
    if (!diag)
        wmma::store_matrix_sync(Gp + (ti0 + 1) * 16 * C + tj0 * 16, acc[2], C, wmma::mem_row_major);
    wmma::store_matrix_sync(Gp + (ti0 + 1) * 16 * C + (tj0 + 1) * 16, acc[3], C, wmma::mem_row_major);

    if (ldr) {
#pragma unroll
        for (int q = 0; q < 4; q++) {
            rs[q] += __shfl_xor_sync(0xffffffffu, rs[q], 1);
            rs[q] += __shfl_xor_sync(0xffffffffu, rs[q], 2);
            rs[q] += __shfl_xor_sync(0xffffffffu, rs[q], 4);
        }
        if (seg == 0) {
#pragma unroll
            for (int q = 0; q < 4; q++) g_s[ks][b][r0 + q * 32] = rs[q];
        }
    }
}

// ===================== stats: mu, trace (diag is in upper tiles) ============
__global__ __launch_bounds__(128)
void stats_k() {
    const int b = blockIdx.x, t = threadIdx.x, w = t >> 5, lane = t & 31;
    __shared__ float red[4];
    const float invn = 1.0f / (float)HW;
    float s = 0.f, g = 0.f;
#pragma unroll
    for (int p = 0; p < KSPLIT; p++) { s += g_s[p][b][t]; g += g_G[p][b][t][t]; }
    const float m = s * invn;
    g_mu[b][t] = m;
    float d = g * invn - m * m;
#pragma unroll
    for (int o = 16; o; o >>= 1) d += __shfl_down_sync(0xffffffffu, d, o);
    if (lane == 0) red[w] = d;
    __syncthreads();
    if (t == 0) g_tr[b] = red[0] + red[1] + red[2] + red[3];
}

// ===================== reduce upper G partials to triu-linear ===============
__global__ __launch_bounds__(256)
void reduce_g() {
    const int b = blockIdx.y;
    const int pos = blockIdx.x * 256 + threadIdx.x;
    if (pos >= TRIU) return;
    int i, j;
    triu_ij(pos, i, j);
    float g = 0.f;
#pragma unroll
    for (int p = 0; p < KSPLIT; p++) g += g_G[p][b][i][j];
    g_Gt[b][pos] = g;
}

// ===================== init: Y0 (mirrored, exact-symmetric) + W0 ============
__global__ __launch_bounds__(256)
void init_tri() {
    const int b = blockIdx.y;
    const int pos = blockIdx.x * 256 + threadIdx.x;
    if (pos >= TRIU) return;
    int i, j;
    triu_ij(pos, i, j);
    const float invn = 1.0f / (float)HW;
    const float invtr = 1.0f / g_tr[b];
    const float y0 = rtf32((g_Gt[b][pos] * invn - g_mu[b][i] * g_mu[b][j]) * invtr);
    const float w0 = -0.5f * y0;   // exact in tf32
    g_Y[0][b][i * C + j] = y0;
    g_Y[0][b][j * C + i] = y0;
    g_W[b][i * C + j] = w0;
    g_W[b][j * C + i] = w0;
}

// ===================== gemmW: W = rna(-0.5 * Z@Y) ===========================
// grid (4, BATCH), 256 thr / 8 warps; warp: tile-row rb*2+(w>>2), col-pair w&3.
__global__ __launch_bounds__(256)
void gemmW(int cur) {
    const int rb = blockIdx.x, b = blockIdx.y;
    const int t = threadIdx.x, w = t >> 5;
    const float* A = g_Z[cur][b];
    const float* Bm = g_Y[cur][b];
    float* D = g_W[b];
    const int trow = rb * 2 + (w >> 2);
    const int jc0 = (w & 3) * 2, jc1 = jc0 + 1;

    AccFrag acc0, acc1;
    wmma::fill_fragment(acc0, 0.0f);
    wmma::fill_fragment(acc1, 0.0f);
#pragma unroll 4
    for (int k0 = 0; k0 < C; k0 += 8) {
        AFragR af; BFragR bf0, bf1;
        wmma::load_matrix_sync(af, A + trow * 16 * C + k0, C);
        wmma::load_matrix_sync(bf0, Bm + k0 * C + jc0 * 16, C);
        wmma::load_matrix_sync(bf1, Bm + k0 * C + jc1 * 16, C);
        wmma::mma_sync(acc0, af, bf0, acc0);
        wmma::mma_sync(acc1, af, bf1, acc1);
    }
#pragma unroll
    for (int e = 0; e < acc0.num_elements; e++) {
        acc0.x[e] = rtf32(-0.5f * acc0.x[e]);
        acc1.x[e] = rtf32(-0.5f * acc1.x[e]);
    }
    wmma::store_matrix_sync(D + trow * 16 * C + jc0 * 16, acc0, C, wmma::mem_row_major);
    wmma::store_matrix_sync(D + trow * 16 * C + jc1 * 16, acc1, C, wmma::mem_row_major);
}

// ===================== gemmYZ: Mnew = rna(M@W + 1.5 M) ======================
// grid (4, roles, BATCH). it==0 && role==1: Z1 = W0 + 1.5I elementwise.
__global__ __launch_bounds__(256)
void gemmYZ(int cur, int nxt, int it, int last) {
    const int rb = blockIdx.x, role = blockIdx.y, b = blockIdx.z;
    const int t = threadIdx.x, w = t >> 5;

    if (it == 0 && role == 1) {
        const int base = rb * 32 * C + t * 16;
#pragma unroll
        for (int q = 0; q < 16; q++) {
            const int e = base + q;
            const int i = e >> 7, j = e & 127;
            float v = g_W[b][e];
            if (i == j) v = rtf32(v + 1.5f);
            g_Z[nxt][b][e] = v;
        }
        return;
    }

    __shared__ __align__(16) float I0[8 * 16], I1[8 * 16];
    if (t < 128) {
        const int r = t >> 4, cc = t & 15;
        I0[r * 16 + cc] = (cc == r) ? 1.5f : 0.0f;
        I1[r * 16 + cc] = (cc == r + 8) ? 1.5f : 0.0f;
    }
    __syncthreads();

    const float* A = role ? g_Z[cur][b] : g_Y[cur][b];
    float* D = role ? g_Z[nxt][b] : g_Y[nxt][b];
    const float* Bm = g_W[b];
    const int trow = rb * 2 + (w >> 2);
    const int jc0 = (w & 3) * 2, jc1 = jc0 + 1;

    AccFrag acc0, acc1;
    wmma::fill_fragment(acc0, 0.0f);
    wmma::fill_fragment(acc1, 0.0f);
#pragma unroll 4
    for (int k0 = 0; k0 < C; k0 += 8) {
        AFragR af; BFragR bf0, bf1;
        wmma::load_matrix_sync(af, A + trow * 16 * C + k0, C);
        wmma::load_matrix_sync(bf0, Bm + k0 * C + jc0 * 16, C);
        wmma::load_matrix_sync(bf1, Bm + k0 * C + jc1 * 16, C);
        wmma::mma_sync(acc0, af, bf0, acc0);
        wmma::mma_sync(acc1, af, bf1, acc1);
    }
    // + 1.5*M via identity MMAs (exact: products exact in fp32 accumulate)
    {
        BFragR i0f, i1f;
        wmma::load_matrix_sync(i0f, I0, 16);
        wmma::load_matrix_sync(i1f, I1, 16);
        AFragR aj;
        wmma::load_matrix_sync(aj, A + trow * 16 * C + jc0 * 16, C);
        wmma::mma_sync(acc0, aj, i0f, acc0);
        wmma::load_matrix_sync(aj, A + trow * 16 * C + jc0 * 16 + 8, C);
        wmma::mma_sync(acc0, aj, i1f, acc0);
        wmma::load_matrix_sync(aj, A + trow * 16 * C + jc1 * 16, C);
        wmma::mma_sync(acc1, aj, i0f, acc1);
        wmma::load_matrix_sync(aj, A + trow * 16 * C + jc1 * 16 + 8, C);
        wmma::mma_sync(acc1, aj, i1f, acc1);
    }
    if (!last) {
#pragma unroll
        for (int e = 0; e < acc0.num_elements; e++) {
            acc0.x[e] = rtf32(acc0.x[e]);
            acc1.x[e] = rtf32(acc1.x[e]);
        }
    }
    wmma::store_matrix_sync(D + trow * 16 * C + jc0 * 16, acc0, C, wmma::mem_row_major);
    wmma::store_matrix_sync(D + trow * 16 * C + jc1 * 16, acc1, C, wmma::mem_row_major);
}

// ===================== triu output ==========================================
__global__ __launch_bounds__(256)
void triu_out(int sel, float* __restrict__ out) {
    const int b = blockIdx.y;
    const int pos = blockIdx.x * 256 + threadIdx.x;
    if (pos >= TRIU) return;
    int i, j;
    triu_ij(pos, i, j);
    out[(size_t)b * TRIU + pos] = g_Y[sel][b][i * C + j] * sqrtf(g_tr[b]);
}

// =================== launch ==================================================
extern "C" void kernel_launch(void* const* d_in, const int* in_sizes, int n_in,
                              void* d_out, int out_size) {
    const float* x = (const float*)d_in[0];
    float* out = (float*)d_out;

    dim3 g1(KSPLIT, BATCH);
    syrk_tc<<<g1, SYTHR>>>(x);
    stats_k<<<BATCH, 128>>>();
    dim3 gt(33, BATCH);
    reduce_g<<<gt, 256>>>();
    init_tri<<<gt, 256>>>();

    int cur = 0;
    for (int it = 0; it < NUM_ITER; it++) {
        const int last = (it == NUM_ITER - 1) ? 1 : 0;
        if (it > 0) {
            dim3 gw(4, BATCH);
            gemmW<<<gw, 256>>>(cur);
        }
        dim3 gyz(4, last ? 1 : 2, BATCH);
        gemmYZ<<<gyz, 256>>>(cur, 1 - cur, it, last);
        cur ^= 1;
    }
    dim3 go(33, BATCH);
    triu_out<<<go, 256>>>(cur, out);
}